// round 6
// baseline (speedup 1.0000x reference)
#include <cuda_runtime.h>

// HyperTransposeConv: fused octonion ConvTranspose2d.
// x: [8, 512, 64, 64] f32; W: [8, 64, 32, 4, 4] f32; b: [8, 32] f32
// out: [8, 256, 128, 128] f32
//
// Parity-decomposed implicit GEMM, inner loop on packed fma.rn.f32x2
// (2 fp32 MACs/lane/instr -- double the 3-reg FFMA rate on sm_103a).

#define CIN   512
#define COUT  256
#define HIN   64
#define HOUT  128
#define CI_SUB 64
#define CO_SUB 32

// Fused big weight, laid out [tap(ky*4+kx): 16][cin: 512][cout: 256]
__device__ float WBIG[16 * CIN * COUT];
__device__ float BBIG[COUT];

struct CompT { int v[8][8]; };

__global__ void prep_w_kernel(const float* __restrict__ W, CompT comp) {
    int t = blockIdx.x * blockDim.x + threadIdx.x;
    if (t >= 16 * CIN * COUT) return;
    int co  = t & (COUT - 1);
    int ci  = (t >> 8) & (CIN - 1);
    int tap = t >> 17;              // ky*4+kx
    int ky = tap >> 2, kx = tap & 3;
    int j = ci >> 6, a = ci & 63;   // input component, sub-channel
    int i = co >> 5, c = co & 31;   // output component, sub-channel
    int v = comp.v[i][j];
    float s = (v < 0) ? -1.0f : 1.0f;
    int id = (v < 0) ? -v : v;
    WBIG[t] = s * W[((id * CI_SUB + a) * CO_SUB + c) * 16 + ky * 4 + kx];
}

__global__ void prep_b_kernel(const float* __restrict__ bsrc, CompT comp) {
    int co = threadIdx.x;            // 256 threads
    int i = co >> 5, c = co & 31;
    float s = 0.0f;
    #pragma unroll
    for (int j = 0; j < 8; ++j) {
        int v = comp.v[i][j];
        float sg = (v < 0) ? -1.0f : 1.0f;
        int id = (v < 0) ? -v : v;
        s += sg * bsrc[id * CO_SUB + c];
    }
    BBIG[co] = s;
}

// packed fp32x2 helpers (sm_100+ only; ptxas never auto-fuses these)
__device__ __forceinline__ void ffma2(unsigned long long& d,
                                      unsigned long long a,
                                      unsigned long long b) {
    asm("fma.rn.f32x2 %0, %1, %2, %0;" : "+l"(d) : "l"(a), "l"(b));
}
__device__ __forceinline__ unsigned long long pack2(float x) {
    unsigned long long r;
    asm("mov.b64 %0, {%1, %1};" : "=l"(r) : "f"(x));
    return r;
}

__global__ __launch_bounds__(256) void hconv_kernel(
    const float* __restrict__ x, float* __restrict__ out)
{
    // double-buffered: As[2][16][64] + Bs[2][16][128] = 24 KB
    __shared__ __align__(16) float sm[2 * 16 * 64 + 2 * 16 * 128];
    float* As = sm;                     // 2 x 1024
    float* Bs = sm + 2 * 16 * 64;       // 2 x 2048

    const int tid = threadIdx.x;
    const int tx = tid & 15, ty = tid >> 4;
    const int ty4 = ty * 4, tx8 = tx * 8;

    const int co0 = blockIdx.x * 128;     // cout tile base (0 or 128)
    const int y   = blockIdx.y;           // 0..63 output row (per parity)
    const int z   = blockIdx.z;           // b*4 + parity
    const int b   = z >> 2;
    const int py  = (z >> 1) & 1;
    const int px  = z & 1;

    // transpose-conv taps per parity:  i = (o + pad - k) / stride
    int kyA[2], iyA[2], kxA[2], dxA[2];
    if (py == 0) { kyA[0] = 1; iyA[0] = y;     kyA[1] = 3; iyA[1] = y - 1; }
    else         { kyA[0] = 0; iyA[0] = y + 1; kyA[1] = 2; iyA[1] = y;     }
    if (px == 0) { kxA[0] = 1; dxA[0] = 0;     kxA[1] = 3; dxA[1] = -1;    }
    else         { kxA[0] = 0; dxA[0] = 1;     kxA[1] = 2; dxA[1] = 0;     }

    const int xcol = tid & 63;   // A loader: pixel column
    const int crow = tid >> 6;   // A loader: cin row group (0..3)
    const int bcol = tid & 31;   // B loader: co float4 column
    const int brow = tid >> 5;   // B loader: cin row (0..7)

    // Per-tap (tt = tyi*2 + txi) precomputed base pointers / predicates.
    const float* xb[4];
    const float* wb[4];
    bool okt[4];
    #pragma unroll
    for (int tt = 0; tt < 4; ++tt) {
        const int tyi = tt >> 1, txi = tt & 1;
        const int iy = iyA[tyi];
        const int dx = dxA[txi];
        const bool vy = (unsigned)iy < (unsigned)HIN;
        const bool vx = (unsigned)(xcol + dx) < (unsigned)HIN;
        okt[tt] = vy && vx;
        // fold dx into the base pointer; guard all derefs with okt
        xb[tt] = x + (long long)b * CIN * (HIN * HIN)
                   + (vy ? iy : 0) * HIN + dx;
        wb[tt] = WBIG + ((kyA[tyi] * 4 + kxA[txi]) << 17) + co0;
    }

    unsigned long long acc[4][4];
    #pragma unroll
    for (int i = 0; i < 4; ++i)
        #pragma unroll
        for (int jp = 0; jp < 4; ++jp) acc[i][jp] = 0ull;

    float  ar[4];
    float4 br0, br1;

    // ---- prefetch helpers (select-chain on tap; no local-mem indexing) ----
    #define PREFETCH(it) do {                                                 \
        const int _tap = (it) >> 5;                                           \
        const int _c0  = ((it) & 31) << 4;                                    \
        const float* _xp = (_tap == 0) ? xb[0] : (_tap == 1) ? xb[1]          \
                         : (_tap == 2) ? xb[2] : xb[3];                       \
        const float* _wp = (_tap == 0) ? wb[0] : (_tap == 1) ? wb[1]          \
                         : (_tap == 2) ? wb[2] : wb[3];                       \
        const bool _ok = (_tap == 0) ? okt[0] : (_tap == 1) ? okt[1]          \
                       : (_tap == 2) ? okt[2] : okt[3];                       \
        _Pragma("unroll")                                                     \
        for (int r = 0; r < 4; ++r) {                                         \
            const int cl = crow + r * 4;                                      \
            ar[r] = _ok ? _xp[(_c0 + cl) * (HIN * HIN) + xcol] : 0.0f;        \
        }                                                                     \
        br0 = *(const float4*)&_wp[(_c0 + brow) * COUT + bcol * 4];           \
        br1 = *(const float4*)&_wp[(_c0 + brow + 8) * COUT + bcol * 4];       \
    } while (0)

    #define STORE(bufi) do {                                                  \
        float* _A = As + (bufi) * 1024;                                       \
        float* _B = Bs + (bufi) * 2048;                                       \
        _Pragma("unroll")                                                     \
        for (int r = 0; r < 4; ++r)                                           \
            _A[(crow + r * 4) * 64 + xcol] = ar[r];                           \
        *(float4*)&_B[brow * 128 + bcol * 4]       = br0;                     \
        *(float4*)&_B[(brow + 8) * 128 + bcol * 4] = br1;                     \
    } while (0)

    PREFETCH(0);
    STORE(0);

    for (int it = 0; it < 128; ++it) {
        __syncthreads();
        if (it + 1 < 128) PREFETCH(it + 1);

        const float* A = As + (it & 1) * 1024;
        const float* B = Bs + (it & 1) * 2048;
        #pragma unroll
        for (int k = 0; k < 16; ++k) {
            const float4 a4 = *(const float4*)&A[k * 64 + ty4];
            const ulonglong2 b0 = *(const ulonglong2*)&B[k * 128 + tx8];
            const ulonglong2 b1 = *(const ulonglong2*)&B[k * 128 + tx8 + 4];
            const unsigned long long av[4] =
                { pack2(a4.x), pack2(a4.y), pack2(a4.z), pack2(a4.w) };
            #pragma unroll
            for (int i = 0; i < 4; ++i) {
                ffma2(acc[i][0], av[i], b0.x);
                ffma2(acc[i][1], av[i], b0.y);
                ffma2(acc[i][2], av[i], b1.x);
                ffma2(acc[i][3], av[i], b1.y);
            }
        }
        if (it + 1 < 128) STORE((it + 1) & 1);
    }

    // unpack packed accumulators: pair jp -> (jj=2jp lo, jj=2jp+1 hi)
    float accf[4][8];
    #pragma unroll
    for (int i = 0; i < 4; ++i)
        #pragma unroll
        for (int jp = 0; jp < 4; ++jp) {
            accf[i][2 * jp]     = __uint_as_float((unsigned)acc[i][jp]);
            accf[i][2 * jp + 1] = __uint_as_float((unsigned)(acc[i][jp] >> 32));
        }

    // Epilogue: transpose through smem so global stores are x-contiguous.
    const int oy = 2 * y + py;
    float* outp = out + ((long long)b * COUT) * (HOUT * HOUT);
    const int r0 = tid >> 6;
    const int ox = 2 * xcol + px;
    for (int cb = 0; cb < 4; ++cb) {
        __syncthreads();
        if ((tx >> 2) == cb) {
            #pragma unroll
            for (int jj = 0; jj < 8; ++jj) {
                const int n = (tx & 3) * 8 + jj;   // local co within 32-group
                #pragma unroll
                for (int i = 0; i < 4; ++i)
                    sm[n * 68 + ty4 + i] = accf[i][jj];
            }
        }
        __syncthreads();
        #pragma unroll
        for (int rr = 0; rr < 8; ++rr) {
            const int row = r0 + rr * 4;          // 0..31
            const int co = co0 + cb * 32 + row;
            outp[(co * HOUT + oy) * HOUT + ox] = sm[row * 68 + xcol] + BBIG[co];
        }
    }
}

extern "C" void kernel_launch(void* const* d_in, const int* in_sizes, int n_in,
                              void* d_out, int out_size)
{
    const float* x  = (const float*)d_in[0];
    const float* W  = (const float*)d_in[1];
    const float* bb = (const float*)d_in[2];
    float* out = (float*)d_out;

    // Cayley-Dickson component table (host-side, passed by value: no memcpy)
    CompT comp;
    comp.v[0][0] = 0;
    for (int m = 1; m < 8; m <<= 1)
        for (int i = 0; i < m; ++i)
            for (int j = 0; j < m; ++j) {
                const int a = comp.v[i][j];
                comp.v[i][j + m] = -(a + m);
                comp.v[i + m][j] = a + m;
                comp.v[i + m][j + m] = a;
            }

    prep_w_kernel<<<(16 * CIN * COUT + 255) / 256, 256>>>(W, comp);
    prep_b_kernel<<<1, 256>>>(bb, comp);

    dim3 grid(2, 64, 32);   // (cout tiles, output rows, batch*parity)
    hconv_kernel<<<grid, 256>>>(x, out);
}

// round 7
// speedup vs baseline: 2.1625x; 2.1625x over previous
#include <cuda_runtime.h>
#include <cuda_bf16.h>
#include <cstdint>

// HyperTransposeConv: fused octonion ConvTranspose2d.
// x: [8, 512, 64, 64] f32; W: [8, 64, 32, 4, 4] f32; b: [8, 32] f32
// out: [8, 256, 128, 128] f32
//
// Parity-decomposed implicit GEMM on tensor cores (mma.sync m16n8k16 bf16)
// with bf16x3 split of both operands for fp32-class accuracy:
//   a*w ~= ah*wh + al*wh + ah*wl   (error ~2^-17)

#define CIN   512
#define COUT  256
#define HIN   64
#define HOUT  128
#define CI_SUB 64
#define CO_SUB 32
#define XELEMS (8 * CIN * HIN * HIN)
#define WELEMS (16 * COUT * CIN)

// bf16 hi/lo splits. X in original [b][cin][y][x] layout.
// W fused+K-major: [tap(ky*4+kx)][cout][cin].
__device__ __nv_bfloat16 XH[XELEMS], XL[XELEMS];
__device__ __nv_bfloat16 WHI[WELEMS], WLO[WELEMS];
__device__ float BBIG[COUT];

struct CompT { int v[8][8]; };

__global__ void prep_x_kernel(const float* __restrict__ x) {
    int t = blockIdx.x * blockDim.x + threadIdx.x;
    if (t >= XELEMS) return;
    float v = x[t];
    __nv_bfloat16 h = __float2bfloat16_rn(v);
    XH[t] = h;
    XL[t] = __float2bfloat16_rn(v - __bfloat162float(h));
}

__global__ void prep_w_kernel(const float* __restrict__ W, CompT comp) {
    int t = blockIdx.x * blockDim.x + threadIdx.x;
    if (t >= WELEMS) return;
    int ci  = t & (CIN - 1);
    int co  = (t >> 9) & (COUT - 1);
    int tap = t >> 17;              // ky*4+kx
    int ky = tap >> 2, kx = tap & 3;
    int j = ci >> 6, a = ci & 63;   // input component, sub-channel
    int i = co >> 5, c = co & 31;   // output component, sub-channel
    int v = comp.v[i][j];
    float s = (v < 0) ? -1.0f : 1.0f;
    int id = (v < 0) ? -v : v;
    float w = s * W[((id * CI_SUB + a) * CO_SUB + c) * 16 + ky * 4 + kx];
    __nv_bfloat16 h = __float2bfloat16_rn(w);
    WHI[t] = h;
    WLO[t] = __float2bfloat16_rn(w - __bfloat162float(h));
}

__global__ void prep_b_kernel(const float* __restrict__ bsrc, CompT comp) {
    int co = threadIdx.x;            // 256 threads
    int i = co >> 5, c = co & 31;
    float s = 0.0f;
    #pragma unroll
    for (int j = 0; j < 8; ++j) {
        int v = comp.v[i][j];
        float sg = (v < 0) ? -1.0f : 1.0f;
        int id = (v < 0) ? -v : v;
        s += sg * bsrc[id * CO_SUB + c];
    }
    BBIG[co] = s;
}

// ---------------- tensor-core main kernel ----------------
// Block: 128 pixels (2 output rows x 64 cols, one parity) x 256 couts.
// 512 threads = 16 warps (4 along M x 4 along N); warp tile 32x64.
// K loop: 3 passes (hh, lh, hl) x 4 taps x 32 chunks of 16 cin = 384 steps.

#define A_PITCH 136          // halves per A smem row ([k][pixel]); 272B stride
#define B_PITCH 24           // halves per B smem row ([cout][k]);  48B stride
#define A_BUF   (16 * A_PITCH)
#define B_BUF   (COUT * B_PITCH)
#define NKCH    384

__device__ __forceinline__ void ldsm_x4(uint32_t& r0, uint32_t& r1,
                                        uint32_t& r2, uint32_t& r3,
                                        const void* p) {
    uint32_t a = (uint32_t)__cvta_generic_to_shared(p);
    asm volatile("ldmatrix.sync.aligned.m8n8.x4.shared.b16 {%0,%1,%2,%3}, [%4];"
                 : "=r"(r0), "=r"(r1), "=r"(r2), "=r"(r3) : "r"(a));
}
__device__ __forceinline__ void ldsm_x4t(uint32_t& r0, uint32_t& r1,
                                         uint32_t& r2, uint32_t& r3,
                                         const void* p) {
    uint32_t a = (uint32_t)__cvta_generic_to_shared(p);
    asm volatile("ldmatrix.sync.aligned.m8n8.x4.trans.shared.b16 {%0,%1,%2,%3}, [%4];"
                 : "=r"(r0), "=r"(r1), "=r"(r2), "=r"(r3) : "r"(a));
}
__device__ __forceinline__ void mma16816(float* c, const uint32_t* a,
                                         uint32_t b0, uint32_t b1) {
    asm volatile(
        "mma.sync.aligned.m16n8k16.row.col.f32.bf16.bf16.f32 "
        "{%0,%1,%2,%3}, {%4,%5,%6,%7}, {%8,%9}, {%0,%1,%2,%3};"
        : "+f"(c[0]), "+f"(c[1]), "+f"(c[2]), "+f"(c[3])
        : "r"(a[0]), "r"(a[1]), "r"(a[2]), "r"(a[3]), "r"(b0), "r"(b1));
}

__global__ __launch_bounds__(512, 1) void hconv_mma_kernel(
    float* __restrict__ out)
{
    __shared__ __align__(16) unsigned char smem_raw[35840];
    __nv_bfloat16* As = (__nv_bfloat16*)smem_raw;                    // 2 bufs
    __nv_bfloat16* Bs = (__nv_bfloat16*)(smem_raw + 2 * A_BUF * 2);  // 2 bufs
    float* ep = (float*)smem_raw;            // epilogue reuse: [64 co][132 p]

    const int tid  = threadIdx.x;
    const int lane = tid & 31;
    const int wid  = tid >> 5;
    const int wm = wid & 3;        // warp M index (x32 pixels)
    const int wn = wid >> 2;       // warp N index (x64 couts)

    const int y0 = blockIdx.x * 2;        // parity-row pair (0..63 step 2)
    const int z  = blockIdx.y;            // b*4 + parity
    const int b  = z >> 2;
    const int py = (z >> 1) & 1;
    const int px = z & 1;

    // A-loader geometry: thread covers (c_l, 4 contiguous pixels)
    const int c_l  = tid >> 5;            // 0..15 cin within chunk
    const int quad = tid & 31;            // pixel quad 0..31
    const int yy   = quad >> 4;           // 0/1 output row within block
    const int xx0  = (quad & 15) * 4;     // pixel x base
    // B-loader geometry
    const int bn = tid >> 1;              // cout row 0..255
    const int bh = tid & 1;               // k half (8 bf16)

    // transpose-conv taps per parity for row y = y0+yy
    const int y = y0 + yy;
    int kyA[2], iyA[2], kxA[2], dxA[2];
    if (py == 0) { kyA[0] = 1; iyA[0] = y;     kyA[1] = 3; iyA[1] = y - 1; }
    else         { kyA[0] = 0; iyA[0] = y + 1; kyA[1] = 2; iyA[1] = y;     }
    if (px == 0) { kxA[0] = 1; dxA[0] = 0;     kxA[1] = 3; dxA[1] = -1;    }
    else         { kxA[0] = 0; dxA[0] = 1;     kxA[1] = 2; dxA[1] = 0;     }

    int abase[4]; unsigned vmask[4]; int wtap[4];
    #pragma unroll
    for (int tt = 0; tt < 4; ++tt) {
        const int tyi = tt >> 1, txi = tt & 1;
        const int iy = iyA[tyi], dx = dxA[txi];
        const bool oky = (unsigned)iy < (unsigned)HIN;
        const int iyc = oky ? iy : 0;
        abase[tt] = b * (CIN * HIN * HIN) + iyc * HIN + xx0 + dx;
        unsigned m = 0;
        #pragma unroll
        for (int j = 0; j < 4; ++j)
            if (oky && (unsigned)(xx0 + dx + j) < (unsigned)HIN) m |= 1u << j;
        vmask[tt] = m;
        wtap[tt] = kyA[tyi] * 4 + kxA[txi];
    }

    float acc[2][8][4];
    #pragma unroll
    for (int mt = 0; mt < 2; ++mt)
        #pragma unroll
        for (int nt = 0; nt < 8; ++nt)
            #pragma unroll
            for (int r = 0; r < 4; ++r) acc[mt][nt][r] = 0.0f;

    __nv_bfloat16 ar[4];
    uint4 br;

    #define PREFETCH(kk) do {                                                 \
        const int _pass = (kk) >> 7;                                          \
        const int _rem  = (kk) & 127;                                         \
        const int _tt   = _rem >> 5;                                          \
        const int _c0   = (_rem & 31) << 4;                                   \
        const __nv_bfloat16* _X = (_pass == 1) ? XL : XH;                     \
        const __nv_bfloat16* _W = (_pass == 2) ? WLO : WHI;                   \
        const int _ab = (_tt == 0) ? abase[0] : (_tt == 1) ? abase[1]         \
                      : (_tt == 2) ? abase[2] : abase[3];                     \
        const unsigned _vm = (_tt == 0) ? vmask[0] : (_tt == 1) ? vmask[1]    \
                           : (_tt == 2) ? vmask[2] : vmask[3];                \
        const int _wt = (_tt == 0) ? wtap[0] : (_tt == 1) ? wtap[1]           \
                      : (_tt == 2) ? wtap[2] : wtap[3];                       \
        const int _ao = _ab + (_c0 + c_l) * (HIN * HIN);                      \
        _Pragma("unroll")                                                     \
        for (int j = 0; j < 4; ++j)                                           \
            ar[j] = (_vm >> j & 1) ? _X[_ao + j] : __nv_bfloat16(0.f);        \
        br = *(const uint4*)&_W[(_wt * COUT + bn) * CIN + _c0 + bh * 8];      \
    } while (0)

    #define STOREB(bufi) do {                                                 \
        __nv_bfloat16* _A = As + (bufi) * A_BUF;                              \
        __nv_bfloat16* _B = Bs + (bufi) * B_BUF;                              \
        _Pragma("unroll")                                                     \
        for (int j = 0; j < 4; ++j)                                           \
            _A[c_l * A_PITCH + quad * 4 + j] = ar[j];                         \
        *(uint4*)&_B[bn * B_PITCH + bh * 8] = br;                             \
    } while (0)

    PREFETCH(0);
    STOREB(0);

    for (int kk = 0; kk < NKCH; ++kk) {
        __syncthreads();
        if (kk + 1 < NKCH) PREFETCH(kk + 1);

        const __nv_bfloat16* A = As + (kk & 1) * A_BUF;
        const __nv_bfloat16* B = Bs + (kk & 1) * B_BUF;

        // A fragments: 2 m16k16 tiles via ldmatrix.x4.trans from [k][p]
        uint32_t af[2][4];
        #pragma unroll
        for (int mt = 0; mt < 2; ++mt) {
            const int krow = (lane & 7) + 8 * (lane >> 4);
            const int mcol = wm * 32 + mt * 16 + 8 * ((lane >> 3) & 1);
            ldsm_x4t(af[mt][0], af[mt][1], af[mt][2], af[mt][3],
                     A + krow * A_PITCH + mcol);
        }
        // B fragments: 8 n8k16 tiles (4 x ldmatrix.x4 over n16 pairs)
        uint32_t bf[8][2];
        #pragma unroll
        for (int pr = 0; pr < 4; ++pr) {
            const int nrow = wn * 64 + pr * 16 + (lane & 7) + 8 * ((lane >> 3) & 1);
            const int kcol = 8 * (lane >> 4);
            uint32_t r0, r1, r2, r3;
            ldsm_x4(r0, r1, r2, r3, B + nrow * B_PITCH + kcol);
            bf[pr * 2][0] = r0;     bf[pr * 2][1] = r2;
            bf[pr * 2 + 1][0] = r1; bf[pr * 2 + 1][1] = r3;
        }
        #pragma unroll
        for (int mt = 0; mt < 2; ++mt)
            #pragma unroll
            for (int nt = 0; nt < 8; ++nt)
                mma16816(acc[mt][nt], af[mt], bf[nt][0], bf[nt][1]);

        if (kk + 1 < NKCH) STOREB((kk + 1) & 1);
    }

    // ---- epilogue: stage [64 co][128 p] chunks through smem ----
    const long long outb = (long long)b * COUT * (HOUT * HOUT);
    for (int cb = 0; cb < 4; ++cb) {
        __syncthreads();
        if (wn == cb) {
            #pragma unroll
            for (int mt = 0; mt < 2; ++mt) {
                const int row0 = wm * 32 + mt * 16 + (lane >> 2);
                #pragma unroll
                for (int nt = 0; nt < 8; ++nt) {
                    const int col0 = nt * 8 + (lane & 3) * 2;
                    ep[col0 * 132 + row0]           = acc[mt][nt][0];
                    ep[(col0 + 1) * 132 + row0]     = acc[mt][nt][1];
                    ep[col0 * 132 + row0 + 8]       = acc[mt][nt][2];
                    ep[(col0 + 1) * 132 + row0 + 8] = acc[mt][nt][3];
                }
            }
        }
        __syncthreads();
        // coalesced-ish stores: 8 contiguous pixels per thread, stride-2 ox
        const int pg = tid & 15;
        const int p0 = pg * 8;
        const int syy = p0 >> 6;
        const int sxx = p0 & 63;
        const int oy = 2 * (y0 + syy) + py;
        #pragma unroll
        for (int it = 0; it < 2; ++it) {
            const int co_l = (tid >> 4) + it * 32;
            const int co = cb * 64 + co_l;
            const float bias = BBIG[co];
            float* op = out + outb + ((long long)co * HOUT + oy) * HOUT + px;
            #pragma unroll
            for (int j = 0; j < 8; ++j)
                op[2 * (sxx + j)] = ep[co_l * 132 + p0 + j] + bias;
        }
    }
}

extern "C" void kernel_launch(void* const* d_in, const int* in_sizes, int n_in,
                              void* d_out, int out_size)
{
    const float* x  = (const float*)d_in[0];
    const float* W  = (const float*)d_in[1];
    const float* bb = (const float*)d_in[2];
    float* out = (float*)d_out;

    // Cayley-Dickson component table (host-side, passed by value: no memcpy)
    CompT comp;
    comp.v[0][0] = 0;
    for (int m = 1; m < 8; m <<= 1)
        for (int i = 0; i < m; ++i)
            for (int j = 0; j < m; ++j) {
                const int a = comp.v[i][j];
                comp.v[i][j + m] = -(a + m);
                comp.v[i + m][j] = a + m;
                comp.v[i + m][j + m] = a;
            }

    prep_x_kernel<<<(XELEMS + 255) / 256, 256>>>(x);
    prep_w_kernel<<<(WELEMS + 255) / 256, 256>>>(W, comp);
    prep_b_kernel<<<1, 256>>>(bb, comp);

    dim3 grid(32, 32);   // (row pairs, batch*parity)
    hconv_mma_kernel<<<grid, 512>>>(out);
}

// round 14
// speedup vs baseline: 2.5825x; 1.1942x over previous
#include <cuda_runtime.h>
#include <cuda_bf16.h>
#include <cstdint>

// HyperTransposeConv: fused octonion ConvTranspose2d.
// x: [8, 512, 64, 64] f32; W: [8, 64, 32, 4, 4] f32; b: [8, 32] f32
// out: [8, 256, 128, 128] f32
//
// Parity-decomposed implicit GEMM on mma.sync (m16n8k16 bf16), bf16x3 split
// a*w ~= ah*wh + al*wh + ah*wl. cp.async 3-stage pipeline; register-level
// operand reuse across the 3 passes (12 ldmatrix.x4 per 48 mma per warp).

#define CIN   512
#define COUT  256
#define HIN   64
#define HOUT  128
#define CI_SUB 64
#define CO_SUB 32
#define XELEMS (8 * CIN * HIN * HIN)
#define WELEMS (16 * COUT * CIN)

// X channel-last [b][y][x][cin] bf16 hi/lo; W fused [tap][cout][cin] hi/lo.
__device__ __nv_bfloat16 XTH[XELEMS], XTL[XELEMS];
__device__ __nv_bfloat16 WHI[WELEMS], WLO[WELEMS];
__device__ float BBIG[COUT];

struct CompT { int v[8][8]; };

// ---------------- prep kernels ----------------

__global__ __launch_bounds__(256) void prep_x_kernel(const float* __restrict__ x)
{
    // block: one (b, y, 128-cin tile); transpose via padded smem (pitch 130)
    __shared__ __nv_bfloat16 shh[64 * 130], shl[64 * 130];
    const int b  = blockIdx.x >> 8;
    const int y  = (blockIdx.x >> 2) & 63;
    const int c0 = (blockIdx.x & 3) * 128;
    const int tid = threadIdx.x;
    #pragma unroll 4
    for (int i = 0; i < 32; ++i) {
        int idx = tid + i * 256;
        int ci = idx >> 6, xx = idx & 63;
        float v = x[(((long long)b * CIN + c0 + ci) * HIN + y) * HIN + xx];
        __nv_bfloat16 h = __float2bfloat16_rn(v);
        shh[xx * 130 + ci] = h;
        shl[xx * 130 + ci] = __float2bfloat16_rn(v - __bfloat162float(h));
    }
    __syncthreads();
    #pragma unroll 4
    for (int j = 0; j < 32; ++j) {
        int idx = tid + j * 256;
        int xx = idx >> 7, c = idx & 127;
        long long o = ((long long)(b * 64 + y) * 64 + xx) * 512 + c0 + c;
        XTH[o] = shh[xx * 130 + c];
        XTL[o] = shl[xx * 130 + c];
    }
}

__global__ void prep_w_kernel(const float* __restrict__ W, CompT comp) {
    int t = blockIdx.x * blockDim.x + threadIdx.x;
    if (t >= WELEMS) return;
    int ci  = t & (CIN - 1);
    int co  = (t >> 9) & (COUT - 1);
    int tap = t >> 17;              // ky*4+kx
    int ky = tap >> 2, kx = tap & 3;
    int j = ci >> 6, a = ci & 63;   // input component, sub-channel
    int i = co >> 5, c = co & 31;   // output component, sub-channel
    int v = comp.v[i][j];
    float s = (v < 0) ? -1.0f : 1.0f;
    int id = (v < 0) ? -v : v;
    float w = s * W[((id * CI_SUB + a) * CO_SUB + c) * 16 + ky * 4 + kx];
    __nv_bfloat16 h = __float2bfloat16_rn(w);
    WHI[t] = h;
    WLO[t] = __float2bfloat16_rn(w - __bfloat162float(h));
}

__global__ void prep_b_kernel(const float* __restrict__ bsrc, CompT comp) {
    int co = threadIdx.x;            // 256 threads
    int i = co >> 5, c = co & 31;
    float s = 0.0f;
    #pragma unroll
    for (int j = 0; j < 8; ++j) {
        int v = comp.v[i][j];
        float sg = (v < 0) ? -1.0f : 1.0f;
        int id = (v < 0) ? -v : v;
        s += sg * bsrc[id * CO_SUB + c];
    }
    BBIG[co] = s;
}

// ---------------- warp-mma plumbing ----------------

__device__ __forceinline__ void ldsm4(uint32_t& r0, uint32_t& r1,
                                      uint32_t& r2, uint32_t& r3, uint32_t a) {
    asm volatile("ldmatrix.sync.aligned.m8n8.x4.shared.b16 {%0,%1,%2,%3}, [%4];"
                 : "=r"(r0), "=r"(r1), "=r"(r2), "=r"(r3) : "r"(a));
}
__device__ __forceinline__ void mma16816(float* c, const uint32_t* a,
                                         uint32_t b0, uint32_t b1) {
    asm volatile(
        "mma.sync.aligned.m16n8k16.row.col.f32.bf16.bf16.f32 "
        "{%0,%1,%2,%3}, {%4,%5,%6,%7}, {%8,%9}, {%0,%1,%2,%3};"
        : "+f"(c[0]), "+f"(c[1]), "+f"(c[2]), "+f"(c[3])
        : "r"(a[0]), "r"(a[1]), "r"(a[2]), "r"(a[3]), "r"(b0), "r"(b1));
}
__device__ __forceinline__ void cp16(uint32_t dst, const void* src, uint32_t sz) {
    asm volatile("cp.async.cg.shared.global [%0], [%1], 16, %2;"
                 :: "r"(dst), "l"(src), "r"(sz) : "memory");
}
#define CP_COMMIT() asm volatile("cp.async.commit_group;" ::: "memory")
#define CP_WAIT(n)  asm volatile("cp.async.wait_group %0;" :: "n"(n) : "memory")

// ---------------- main kernel ----------------
// CTA tile: M=128 pixels (2 rows x 64) x N=256 couts. 512 thr = 16 warps
// (4M x 4N), warp tile 32x64. Chunks: 4 taps x 16 c32 = 64; 2 k16 per chunk.
// smem per stage: A[2hl][128pix][32cin] pitch 80B (20480B)
//               + B[2hl][256co][32cin] pitch 80B (40960B) = 61440B; 3 stages.

#define PITCH  80
#define A_HL   10240
#define A_SZ   20480
#define B_HL   20480
#define STAGE  61440
#define NCHUNK 64
#define SMEM_BYTES (3 * STAGE)

__global__ __launch_bounds__(512, 1) void hconv_mma2_kernel(float* __restrict__ out)
{
    extern __shared__ __align__(16) char smem[];
    const uint32_t sb = (uint32_t)__cvta_generic_to_shared(smem);
    float* ep = (float*)smem;     // epilogue reuse: [64 co][132 p]

    const int tid  = threadIdx.x;
    const int lane = tid & 31;
    const int wid  = tid >> 5;
    const int wm = wid & 3;        // warp M index (x32 pixels)
    const int wn = wid >> 2;       // warp N index (x64 couts)

    const int y0 = blockIdx.x * 2;        // output-row pair (per parity)
    const int z  = blockIdx.y;            // b*4 + parity
    const int b  = z >> 2;
    const int py = (z >> 1) & 1;
    const int px = z & 1;

    // ---- A loader: thread -> (pixel, hl, quarter-pair) ----
    const int ap  = tid & 127;            // pixel row
    const int ahl = (tid >> 7) & 1;       // hi(0)/lo(1) split
    const int aq0 = tid >> 8;             // quarters {aq0, aq0+2}
    const int ayy = ap >> 6, axx = ap & 63;
    const int ay  = y0 + ayy;
    // ---- B loader: thread -> (cout, hl, 4 quarters) ----
    const int bco = tid & 255;
    const int bhl = (tid >> 8) & 1;

    // taps for this pixel's row/parity
    int kyA[2], iyA[2], kxA[2], dxA[2];
    if (py == 0) { kyA[0] = 1; iyA[0] = ay;     kyA[1] = 3; iyA[1] = ay - 1; }
    else         { kyA[0] = 0; iyA[0] = ay + 1; kyA[1] = 2; iyA[1] = ay;     }
    if (px == 0) { kxA[0] = 1; dxA[0] = 0;      kxA[1] = 3; dxA[1] = -1;     }
    else         { kxA[0] = 0; dxA[0] = 1;      kxA[1] = 2; dxA[1] = 0;      }

    const char* asrc[4]; uint32_t asz[4]; int wtap[4];
    const char* xbase = (const char*)(ahl ? XTL : XTH);
    #pragma unroll
    for (int tt = 0; tt < 4; ++tt) {
        const int tyi = tt >> 1, txi = tt & 1;
        const int iy = iyA[tyi];
        const int ix = axx + dxA[txi];
        const bool ok = (unsigned)iy < (unsigned)HIN && (unsigned)ix < (unsigned)HIN;
        asz[tt]  = ok ? 16u : 0u;
        asrc[tt] = xbase + ((long long)(b * 64 + (ok ? iy : 0)) * 64
                            + (ok ? ix : 0)) * 1024;   // 512 cin * 2B
        wtap[tt] = kyA[tyi] * 4 + kxA[txi];
    }
    const char* wbase = (const char*)(bhl ? WLO : WHI) + (long long)bco * 1024;

    const uint32_t dA0 = sb + ahl * A_HL + ap * PITCH;
    const uint32_t dB0 = sb + A_SZ + bhl * B_HL + bco * PITCH;

    // ldmatrix row offsets (invariant)
    const int mrow  = (lane & 7) + 8 * ((lane >> 3) & 1);
    const int khalf = lane >> 4;
    uint32_t a_off[2], b_off[4];
    #pragma unroll
    for (int mt = 0; mt < 2; ++mt)
        a_off[mt] = (wm * 32 + mt * 16 + mrow) * PITCH + khalf * 16;
    #pragma unroll
    for (int pr = 0; pr < 4; ++pr)
        b_off[pr] = (wn * 64 + pr * 16 + mrow) * PITCH + khalf * 16;

    float acc[2][8][4];
    #pragma unroll
    for (int mt = 0; mt < 2; ++mt)
        #pragma unroll
        for (int nt = 0; nt < 8; ++nt)
            #pragma unroll
            for (int r = 0; r < 4; ++r) acc[mt][nt][r] = 0.0f;

    #define ISSUE(chunk, stage) do {                                          \
        const int _tap = (chunk) >> 4;                                        \
        const int _c0b = ((chunk) & 15) * 64;        /* 32 cin * 2B */        \
        const char* _xs = ((_tap == 0) ? asrc[0] : (_tap == 1) ? asrc[1]      \
                         : (_tap == 2) ? asrc[2] : asrc[3]) + _c0b;           \
        const uint32_t _sz = (_tap == 0) ? asz[0] : (_tap == 1) ? asz[1]      \
                           : (_tap == 2) ? asz[2] : asz[3];                   \
        const int _wt = (_tap == 0) ? wtap[0] : (_tap == 1) ? wtap[1]         \
                      : (_tap == 2) ? wtap[2] : wtap[3];                      \
        const uint32_t _dA = dA0 + (stage) * STAGE;                           \
        cp16(_dA + aq0 * 16,      _xs + aq0 * 16,      _sz);                  \
        cp16(_dA + aq0 * 16 + 32, _xs + aq0 * 16 + 32, _sz);                  \
        const char* _ws = wbase + (long long)_wt * (256 * 1024) + _c0b;       \
        const uint32_t _dB = dB0 + (stage) * STAGE;                           \
        _Pragma("unroll")                                                     \
        for (int _q = 0; _q < 4; ++_q)                                        \
            cp16(_dB + _q * 16, _ws + _q * 16, 16u);                          \
        CP_COMMIT();                                                          \
    } while (0)

    ISSUE(0, 0);
    ISSUE(1, 1);

    for (int i = 0; i < NCHUNK; ++i) {
        const int st = i - (i / 3) * 3;          // i % 3
        CP_WAIT(1);
        __syncthreads();
        if (i + 2 < NCHUNK) {
            const int st2 = (i + 2) - ((i + 2) / 3) * 3;
            ISSUE(i + 2, st2);
        }

        const uint32_t Ab = sb + st * STAGE;
        const uint32_t Bb = Ab + A_SZ;
        #pragma unroll
        for (int ks = 0; ks < 2; ++ks) {
            uint32_t ah[2][4], al[2][4], bf[8][2];
            #pragma unroll
            for (int mt = 0; mt < 2; ++mt)
                ldsm4(ah[mt][0], ah[mt][1], ah[mt][2], ah[mt][3],
                      Ab + a_off[mt] + ks * 32);
            #pragma unroll
            for (int mt = 0; mt < 2; ++mt)
                ldsm4(al[mt][0], al[mt][1], al[mt][2], al[mt][3],
                      Ab + A_HL + a_off[mt] + ks * 32);
            #pragma unroll
            for (int pr = 0; pr < 4; ++pr) {
                uint32_t r0, r1, r2, r3;
                ldsm4(r0, r1, r2, r3, Bb + b_off[pr] + ks * 32);
                bf[pr * 2][0] = r0;     bf[pr * 2][1] = r2;
                bf[pr * 2 + 1][0] = r1; bf[pr * 2 + 1][1] = r3;
            }
            #pragma unroll
            for (int mt = 0; mt < 2; ++mt)
                #pragma unroll
                for (int nt = 0; nt < 8; ++nt)
                    mma16816(acc[mt][nt], ah[mt], bf[nt][0], bf[nt][1]);
            #pragma unroll
            for (int mt = 0; mt < 2; ++mt)
                #pragma unroll
                for (int nt = 0; nt < 8; ++nt)
                    mma16816(acc[mt][nt], al[mt], bf[nt][0], bf[nt][1]);
            #pragma unroll
            for (int pr = 0; pr < 4; ++pr) {
                uint32_t r0, r1, r2, r3;
                ldsm4(r0, r1, r2, r3, Bb + B_HL + b_off[pr] + ks * 32);
                bf[pr * 2][0] = r0;     bf[pr * 2][1] = r2;
                bf[pr * 2 + 1][0] = r1; bf[pr * 2 + 1][1] = r3;
            }
            #pragma unroll
            for (int mt = 0; mt < 2; ++mt)
                #pragma unroll
                for (int nt = 0; nt < 8; ++nt)
                    mma16816(acc[mt][nt], ah[mt], bf[nt][0], bf[nt][1]);
        }
    }
    CP_WAIT(0);

    // ---- epilogue: stage [64 co][128 p] chunks through smem ----
    const long long outb = (long long)b * COUT * (HOUT * HOUT);
    for (int cb = 0; cb < 4; ++cb) {
        __syncthreads();
        if (wn == cb) {
            #pragma unroll
            for (int mt = 0; mt < 2; ++mt) {
                const int row0 = wm * 32 + mt * 16 + (lane >> 2);
                #pragma unroll
                for (int nt = 0; nt < 8; ++nt) {
                    const int col0 = nt * 8 + (lane & 3) * 2;
                    ep[col0 * 132 + row0]           = acc[mt][nt][0];
                    ep[(col0 + 1) * 132 + row0]     = acc[mt][nt][1];
                    ep[col0 * 132 + row0 + 8]       = acc[mt][nt][2];
                    ep[(col0 + 1) * 132 + row0 + 8] = acc[mt][nt][3];
                }
            }
        }
        __syncthreads();
        // 8 contiguous pixels per thread, stride-2 ox stores
        const int pg = tid & 15;
        const int p0 = pg * 8;
        const int syy = p0 >> 6;
        const int sxx = p0 & 63;
        const int oy = 2 * (y0 + syy) + py;
        #pragma unroll
        for (int it = 0; it < 2; ++it) {
            const int co_l = (tid >> 4) + it * 32;
            const int co = cb * 64 + co_l;
            const float bias = BBIG[co];
            float* op = out + outb + ((long long)co * HOUT + oy) * HOUT + px;
            #pragma unroll
            for (int j = 0; j < 8; ++j)
                op[2 * (sxx + j)] = ep[co_l * 132 + p0 + j] + bias;
        }
    }
}

// ---------------- host launcher ----------------

extern "C" void kernel_launch(void* const* d_in, const int* in_sizes, int n_in,
                              void* d_out, int out_size)
{
    const float* x  = (const float*)d_in[0];
    const float* W  = (const float*)d_in[1];
    const float* bb = (const float*)d_in[2];
    float* out = (float*)d_out;

    // Cayley-Dickson component table (host-side, passed by value: no memcpy)
    CompT comp;
    comp.v[0][0] = 0;
    for (int m = 1; m < 8; m <<= 1)
        for (int i = 0; i < m; ++i)
            for (int j = 0; j < m; ++j) {
                const int a = comp.v[i][j];
                comp.v[i][j + m] = -(a + m);
                comp.v[i + m][j] = a + m;
                comp.v[i + m][j + m] = a;
            }

    cudaFuncSetAttribute(hconv_mma2_kernel,
                         cudaFuncAttributeMaxDynamicSharedMemorySize, SMEM_BYTES);

    prep_x_kernel<<<2048, 256>>>(x);
    prep_w_kernel<<<(WELEMS + 255) / 256, 256>>>(W, comp);
    prep_b_kernel<<<1, 256>>>(bb, comp);

    dim3 grid(32, 32);   // (row pairs, batch*parity)
    hconv_mma2_kernel<<<grid, 512, SMEM_BYTES>>>(out);
}

// round 15
// speedup vs baseline: 3.6996x; 1.4326x over previous
#include <cuda_runtime.h>
#include <cuda_fp16.h>
#include <cstdint>

// HyperTransposeConv: fused octonion ConvTranspose2d.
// x: [8, 512, 64, 64] f32; W: [8, 64, 32, 4, 4] f32; b: [8, 32] f32
// out: [8, 256, 128, 128] f32
//
// Parity-decomposed implicit GEMM on mma.sync (m16n8k16 fp16, fp32 acc).
// fp16x2 split of x only: a*w ~= ah*w + al*w (w single fp16; err ~1.4e-4).
// cp.async 4-stage pipeline, prefetch distance 3.

#define CIN   512
#define COUT  256
#define HIN   64
#define HOUT  128
#define CI_SUB 64
#define CO_SUB 32
#define XELEMS (8 * CIN * HIN * HIN)
#define WELEMS (16 * COUT * CIN)

// X channel-last [b][y][x][cin] fp16 hi/lo; W fused [tap][cout][cin] fp16.
__device__ __half XTH[XELEMS], XTL[XELEMS];
__device__ __half WHI[WELEMS];
__device__ float BBIG[COUT];

struct CompT { int v[8][8]; };

// ---------------- prep kernels ----------------

__global__ __launch_bounds__(256) void prep_x_kernel(const float* __restrict__ x)
{
    // block: one (b, y, 128-cin tile); transpose via padded smem (pitch 130)
    __shared__ __half shh[64 * 130], shl[64 * 130];
    const int b  = blockIdx.x >> 8;
    const int y  = (blockIdx.x >> 2) & 63;
    const int c0 = (blockIdx.x & 3) * 128;
    const int tid = threadIdx.x;
    #pragma unroll 4
    for (int i = 0; i < 32; ++i) {
        int idx = tid + i * 256;
        int ci = idx >> 6, xx = idx & 63;
        float v = x[(((long long)b * CIN + c0 + ci) * HIN + y) * HIN + xx];
        __half h = __float2half_rn(v);
        shh[xx * 130 + ci] = h;
        shl[xx * 130 + ci] = __float2half_rn(v - __half2float(h));
    }
    __syncthreads();
    #pragma unroll 4
    for (int j = 0; j < 32; ++j) {
        int idx = tid + j * 256;
        int xx = idx >> 7, c = idx & 127;
        long long o = ((long long)(b * 64 + y) * 64 + xx) * 512 + c0 + c;
        XTH[o] = shh[xx * 130 + c];
        XTL[o] = shl[xx * 130 + c];
    }
}

__global__ void prep_w_kernel(const float* __restrict__ W, CompT comp) {
    int t = blockIdx.x * blockDim.x + threadIdx.x;
    if (t >= WELEMS) return;
    int ci  = t & (CIN - 1);
    int co  = (t >> 9) & (COUT - 1);
    int tap = t >> 17;              // ky*4+kx
    int ky = tap >> 2, kx = tap & 3;
    int j = ci >> 6, a = ci & 63;   // input component, sub-channel
    int i = co >> 5, c = co & 31;   // output component, sub-channel
    int v = comp.v[i][j];
    float s = (v < 0) ? -1.0f : 1.0f;
    int id = (v < 0) ? -v : v;
    float w = s * W[((id * CI_SUB + a) * CO_SUB + c) * 16 + ky * 4 + kx];
    WHI[t] = __float2half_rn(w);
}

__global__ void prep_b_kernel(const float* __restrict__ bsrc, CompT comp) {
    int co = threadIdx.x;            // 256 threads
    int i = co >> 5, c = co & 31;
    float s = 0.0f;
    #pragma unroll
    for (int j = 0; j < 8; ++j) {
        int v = comp.v[i][j];
        float sg = (v < 0) ? -1.0f : 1.0f;
        int id = (v < 0) ? -v : v;
        s += sg * bsrc[id * CO_SUB + c];
    }
    BBIG[co] = s;
}

// ---------------- warp-mma plumbing ----------------

__device__ __forceinline__ void ldsm4(uint32_t& r0, uint32_t& r1,
                                      uint32_t& r2, uint32_t& r3, uint32_t a) {
    asm volatile("ldmatrix.sync.aligned.m8n8.x4.shared.b16 {%0,%1,%2,%3}, [%4];"
                 : "=r"(r0), "=r"(r1), "=r"(r2), "=r"(r3) : "r"(a));
}
__device__ __forceinline__ void mma16816(float* c, const uint32_t* a,
                                         uint32_t b0, uint32_t b1) {
    asm volatile(
        "mma.sync.aligned.m16n8k16.row.col.f32.f16.f16.f32 "
        "{%0,%1,%2,%3}, {%4,%5,%6,%7}, {%8,%9}, {%0,%1,%2,%3};"
        : "+f"(c[0]), "+f"(c[1]), "+f"(c[2]), "+f"(c[3])
        : "r"(a[0]), "r"(a[1]), "r"(a[2]), "r"(a[3]), "r"(b0), "r"(b1));
}
__device__ __forceinline__ void cp16(uint32_t dst, const void* src, uint32_t sz) {
    asm volatile("cp.async.cg.shared.global [%0], [%1], 16, %2;"
                 :: "r"(dst), "l"(src), "r"(sz) : "memory");
}
#define CP_COMMIT() asm volatile("cp.async.commit_group;" ::: "memory")
#define CP_WAIT(n)  asm volatile("cp.async.wait_group %0;" :: "n"(n) : "memory")

// ---------------- main kernel ----------------
// CTA tile: M=128 pixels (2 rows x 64) x N=256 couts. 512 thr = 16 warps
// (4M x 4N), warp tile 32x64. Chunks: 4 taps x 16 c32 = 64; 2 k16 per chunk.
// smem per stage: A[2hl][128pix][32cin] pitch 80B (20480B)
//               + B[256co][32cin]       pitch 80B (20480B) = 40960B; 4 stages.

#define PITCH  80
#define A_HL   10240
#define A_SZ   20480
#define STAGE  40960
#define NCHUNK 64
#define SMEM_BYTES (4 * STAGE)

__global__ __launch_bounds__(512, 1) void hconv_mma3_kernel(float* __restrict__ out)
{
    extern __shared__ __align__(16) char smem[];
    const uint32_t sb = (uint32_t)__cvta_generic_to_shared(smem);
    float* ep = (float*)smem;     // epilogue reuse: [64 co][132 p]

    const int tid  = threadIdx.x;
    const int lane = tid & 31;
    const int wid  = tid >> 5;
    const int wm = wid & 3;        // warp M index (x32 pixels)
    const int wn = wid >> 2;       // warp N index (x64 couts)

    const int y0 = blockIdx.x * 2;        // output-row pair (per parity)
    const int z  = blockIdx.y;            // b*4 + parity
    const int b  = z >> 2;
    const int py = (z >> 1) & 1;
    const int px = z & 1;

    // ---- loader geometry: row = tid&255, 32B half = tid>>8 ----
    const int row  = tid & 255;
    const int half = tid >> 8;            // 0/1 -> 32B within 64B row
    // A: row = ahl*128 + pixel
    const int ahl = row >> 7;
    const int ap  = row & 127;
    const int ayy = ap >> 6, axx = ap & 63;
    const int ay  = y0 + ayy;

    // taps for this pixel's row/parity
    int kyA[2], iyA[2], kxA[2], dxA[2];
    if (py == 0) { kyA[0] = 1; iyA[0] = ay;     kyA[1] = 3; iyA[1] = ay - 1; }
    else         { kyA[0] = 0; iyA[0] = ay + 1; kyA[1] = 2; iyA[1] = ay;     }
    if (px == 0) { kxA[0] = 1; dxA[0] = 0;      kxA[1] = 3; dxA[1] = -1;     }
    else         { kxA[0] = 0; dxA[0] = 1;      kxA[1] = 2; dxA[1] = 0;      }

    const char* asrc[4]; uint32_t asz[4]; int wtap[4];
    const char* xbase = (const char*)(ahl ? XTL : XTH);
    #pragma unroll
    for (int tt = 0; tt < 4; ++tt) {
        const int tyi = tt >> 1, txi = tt & 1;
        const int iy = iyA[tyi];
        const int ix = axx + dxA[txi];
        const bool ok = (unsigned)iy < (unsigned)HIN && (unsigned)ix < (unsigned)HIN;
        asz[tt]  = ok ? 16u : 0u;
        asrc[tt] = xbase + ((long long)(b * 64 + (ok ? iy : 0)) * 64
                            + (ok ? ix : 0)) * 1024    // 512 cin * 2B
                   + half * 32;
        wtap[tt] = kyA[tyi] * 4 + kxA[txi];
    }
    const char* wbase = (const char*)WHI + (long long)row * 1024 + half * 32;

    const uint32_t dA0 = sb + row * PITCH + half * 32;           // A: row covers hl*pix
    const uint32_t dB0 = sb + A_SZ + row * PITCH + half * 32;    // B: row = cout

    // ldmatrix row offsets (invariant)
    const int mrow  = (lane & 7) + 8 * ((lane >> 3) & 1);
    const int khalf = lane >> 4;
    uint32_t a_off[2], b_off[4];
    #pragma unroll
    for (int mt = 0; mt < 2; ++mt)
        a_off[mt] = (wm * 32 + mt * 16 + mrow) * PITCH + khalf * 16;
    #pragma unroll
    for (int pr = 0; pr < 4; ++pr)
        b_off[pr] = (wn * 64 + pr * 16 + mrow) * PITCH + khalf * 16;

    float acc[2][8][4];
    #pragma unroll
    for (int mt = 0; mt < 2; ++mt)
        #pragma unroll
        for (int nt = 0; nt < 8; ++nt)
            #pragma unroll
            for (int r = 0; r < 4; ++r) acc[mt][nt][r] = 0.0f;

    #define ISSUE(chunk, stage) do {                                          \
        const int _tap = (chunk) >> 4;                                        \
        const int _c0b = ((chunk) & 15) * 64;        /* 32 cin * 2B */        \
        const char* _xs = ((_tap == 0) ? asrc[0] : (_tap == 1) ? asrc[1]      \
                         : (_tap == 2) ? asrc[2] : asrc[3]) + _c0b;           \
        const uint32_t _sz = (_tap == 0) ? asz[0] : (_tap == 1) ? asz[1]      \
                           : (_tap == 2) ? asz[2] : asz[3];                   \
        const int _wt = (_tap == 0) ? wtap[0] : (_tap == 1) ? wtap[1]         \
                      : (_tap == 2) ? wtap[2] : wtap[3];                      \
        const uint32_t _dA = dA0 + (stage) * STAGE;                           \
        cp16(_dA,      _xs,      _sz);                                        \
        cp16(_dA + 16, _xs + 16, _sz);                                        \
        const char* _ws = wbase + (long long)_wt * (256 * 1024) + _c0b;       \
        const uint32_t _dB = dB0 + (stage) * STAGE;                           \
        cp16(_dB,      _ws,      16u);                                        \
        cp16(_dB + 16, _ws + 16, 16u);                                        \
        CP_COMMIT();                                                          \
    } while (0)

    ISSUE(0, 0);
    ISSUE(1, 1);
    ISSUE(2, 2);

    for (int i = 0; i < NCHUNK; ++i) {
        const int st = i & 3;
        CP_WAIT(2);
        __syncthreads();
        if (i + 3 < NCHUNK) ISSUE(i + 3, (i + 3) & 3);

        const uint32_t Ab = sb + st * STAGE;
        const uint32_t Bb = Ab + A_SZ;
        #pragma unroll
        for (int ks = 0; ks < 2; ++ks) {
            uint32_t ah[2][4], al[2][4], bf[8][2];
            #pragma unroll
            for (int pr = 0; pr < 4; ++pr) {
                uint32_t r0, r1, r2, r3;
                ldsm4(r0, r1, r2, r3, Bb + b_off[pr] + ks * 32);
                bf[pr * 2][0] = r0;     bf[pr * 2][1] = r2;
                bf[pr * 2 + 1][0] = r1; bf[pr * 2 + 1][1] = r3;
            }
            #pragma unroll
            for (int mt = 0; mt < 2; ++mt)
                ldsm4(ah[mt][0], ah[mt][1], ah[mt][2], ah[mt][3],
                      Ab + a_off[mt] + ks * 32);
            #pragma unroll
            for (int mt = 0; mt < 2; ++mt)
                ldsm4(al[mt][0], al[mt][1], al[mt][2], al[mt][3],
                      Ab + A_HL + a_off[mt] + ks * 32);
            #pragma unroll
            for (int mt = 0; mt < 2; ++mt)
                #pragma unroll
                for (int nt = 0; nt < 8; ++nt)
                    mma16816(acc[mt][nt], ah[mt], bf[nt][0], bf[nt][1]);
            #pragma unroll
            for (int mt = 0; mt < 2; ++mt)
                #pragma unroll
                for (int nt = 0; nt < 8; ++nt)
                    mma16816(acc[mt][nt], al[mt], bf[nt][0], bf[nt][1]);
        }
    }
    CP_WAIT(0);

    // ---- epilogue: stage [64 co][128 p] chunks through smem ----
    const long long outb = (long long)b * COUT * (HOUT * HOUT);
    for (int cb = 0; cb < 4; ++cb) {
        __syncthreads();
        if (wn == cb) {
            #pragma unroll
            for (int mt = 0; mt < 2; ++mt) {
                const int row0 = wm * 32 + mt * 16 + (lane >> 2);
                #pragma unroll
                for (int nt = 0; nt < 8; ++nt) {
                    const int col0 = nt * 8 + (lane & 3) * 2;
                    ep[col0 * 132 + row0]           = acc[mt][nt][0];
                    ep[(col0 + 1) * 132 + row0]     = acc[mt][nt][1];
                    ep[col0 * 132 + row0 + 8]       = acc[mt][nt][2];
                    ep[(col0 + 1) * 132 + row0 + 8] = acc[mt][nt][3];
                }
            }
        }
        __syncthreads();
        // 8 contiguous pixels per thread, stride-2 ox stores
        const int pg = tid & 15;
        const int p0 = pg * 8;
        const int syy = p0 >> 6;
        const int sxx = p0 & 63;
        const int oy = 2 * (y0 + syy) + py;
        #pragma unroll
        for (int it = 0; it < 2; ++it) {
            const int co_l = (tid >> 4) + it * 32;
            const int co = cb * 64 + co_l;
            const float bias = BBIG[co];
            float* op = out + outb + ((long long)co * HOUT + oy) * HOUT + px;
            #pragma unroll
            for (int j = 0; j < 8; ++j)
                op[2 * (sxx + j)] = ep[co_l * 132 + p0 + j] + bias;
        }
    }
}

// ---------------- host launcher ----------------

extern "C" void kernel_launch(void* const* d_in, const int* in_sizes, int n_in,
                              void* d_out, int out_size)
{
    const float* x  = (const float*)d_in[0];
    const float* W  = (const float*)d_in[1];
    const float* bb = (const float*)d_in[2];
    float* out = (float*)d_out;

    // Cayley-Dickson component table (host-side, passed by value: no memcpy)
    CompT comp;
    comp.v[0][0] = 0;
    for (int m = 1; m < 8; m <<= 1)
        for (int i = 0; i < m; ++i)
            for (int j = 0; j < m; ++j) {
                const int a = comp.v[i][j];
                comp.v[i][j + m] = -(a + m);
                comp.v[i + m][j] = a + m;
                comp.v[i + m][j + m] = a;
            }

    cudaFuncSetAttribute(hconv_mma3_kernel,
                         cudaFuncAttributeMaxDynamicSharedMemorySize, SMEM_BYTES);

    prep_x_kernel<<<2048, 256>>>(x);
    prep_w_kernel<<<(WELEMS + 255) / 256, 256>>>(W, comp);
    prep_b_kernel<<<1, 256>>>(bb, comp);

    dim3 grid(32, 32);   // (row pairs, batch*parity)
    hconv_mma3_kernel<<<grid, 512, SMEM_BYTES>>>(out);
}

// round 17
// speedup vs baseline: 4.8138x; 1.3012x over previous
#include <cuda_runtime.h>
#include <cuda_fp16.h>
#include <cstdint>

// HyperTransposeConv: fused octonion ConvTranspose2d.
// x: [8, 512, 64, 64] f32; W: [8, 64, 32, 4, 4] f32; b: [8, 32] f32
// out: [8, 256, 128, 128] f32
//
// Parity-decomposed implicit GEMM on mma.sync (m16n8k16 fp16, fp32 acc).
// Plain fp16 operands (err ~3e-4 << 1e-3). cp.async 4-stage pipeline.
// 256-thread CTAs, 2 CTAs/SM so barriers of one CTA hide under the other.

#define CIN   512
#define COUT  256
#define HIN   64
#define HOUT  128
#define CI_SUB 64
#define CO_SUB 32
#define XELEMS (8 * CIN * HIN * HIN)
#define WELEMS (16 * COUT * CIN)

// X channel-last [b][y][x][cin] fp16; W fused [tap][cout][cin] fp16.
__device__ __half XTH[XELEMS];
__device__ __half WHI[WELEMS];
__device__ float BBIG[COUT];

struct CompT { int v[8][8]; };

// ---------------- prep kernels ----------------

__global__ __launch_bounds__(256) void prep_x_kernel(const float* __restrict__ x)
{
    // block: one (b, y, 128-cin tile); transpose via padded smem (pitch 130)
    __shared__ __half shh[64 * 130];
    const int b  = blockIdx.x >> 8;
    const int y  = (blockIdx.x >> 2) & 63;
    const int c0 = (blockIdx.x & 3) * 128;
    const int tid = threadIdx.x;
    #pragma unroll 4
    for (int i = 0; i < 32; ++i) {
        int idx = tid + i * 256;
        int ci = idx >> 6, xx = idx & 63;
        float v = x[(((long long)b * CIN + c0 + ci) * HIN + y) * HIN + xx];
        shh[xx * 130 + ci] = __float2half_rn(v);
    }
    __syncthreads();
    #pragma unroll 4
    for (int j = 0; j < 32; ++j) {
        int idx = tid + j * 256;
        int xx = idx >> 7, c = idx & 127;
        long long o = ((long long)(b * 64 + y) * 64 + xx) * 512 + c0 + c;
        XTH[o] = shh[xx * 130 + c];
    }
}

__global__ void prep_w_kernel(const float* __restrict__ W, CompT comp) {
    int t = blockIdx.x * blockDim.x + threadIdx.x;
    if (t >= WELEMS) return;
    int ci  = t & (CIN - 1);
    int co  = (t >> 9) & (COUT - 1);
    int tap = t >> 17;              // ky*4+kx
    int ky = tap >> 2, kx = tap & 3;
    int j = ci >> 6, a = ci & 63;   // input component, sub-channel
    int i = co >> 5, c = co & 31;   // output component, sub-channel
    int v = comp.v[i][j];
    float s = (v < 0) ? -1.0f : 1.0f;
    int id = (v < 0) ? -v : v;
    float w = s * W[((id * CI_SUB + a) * CO_SUB + c) * 16 + ky * 4 + kx];
    WHI[t] = __float2half_rn(w);
}

__global__ void prep_b_kernel(const float* __restrict__ bsrc, CompT comp) {
    int co = threadIdx.x;            // 256 threads
    int i = co >> 5, c = co & 31;
    float s = 0.0f;
    #pragma unroll
    for (int j = 0; j < 8; ++j) {
        int v = comp.v[i][j];
        float sg = (v < 0) ? -1.0f : 1.0f;
        int id = (v < 0) ? -v : v;
        s += sg * bsrc[id * CO_SUB + c];
    }
    BBIG[co] = s;
}

// ---------------- warp-mma plumbing ----------------

__device__ __forceinline__ void ldsm4(uint32_t& r0, uint32_t& r1,
                                      uint32_t& r2, uint32_t& r3, uint32_t a) {
    asm volatile("ldmatrix.sync.aligned.m8n8.x4.shared.b16 {%0,%1,%2,%3}, [%4];"
                 : "=r"(r0), "=r"(r1), "=r"(r2), "=r"(r3) : "r"(a));
}
__device__ __forceinline__ void mma16816(float* c, const uint32_t* a,
                                         uint32_t b0, uint32_t b1) {
    asm volatile(
        "mma.sync.aligned.m16n8k16.row.col.f32.f16.f16.f32 "
        "{%0,%1,%2,%3}, {%4,%5,%6,%7}, {%8,%9}, {%0,%1,%2,%3};"
        : "+f"(c[0]), "+f"(c[1]), "+f"(c[2]), "+f"(c[3])
        : "r"(a[0]), "r"(a[1]), "r"(a[2]), "r"(a[3]), "r"(b0), "r"(b1));
}
__device__ __forceinline__ void cp16(uint32_t dst, const void* src, uint32_t sz) {
    asm volatile("cp.async.cg.shared.global [%0], [%1], 16, %2;"
                 :: "r"(dst), "l"(src), "r"(sz) : "memory");
}
#define CP_COMMIT() asm volatile("cp.async.commit_group;" ::: "memory")
#define CP_WAIT(n)  asm volatile("cp.async.wait_group %0;" :: "n"(n) : "memory")

// ---------------- main kernel ----------------
// CTA tile: M=64 pixels (1 output row per parity) x N=256 couts.
// 256 thr = 8 warps (2M x 4N), warp tile 32x64.
// Chunks: 4 taps x 16 c32 = 64; 2 k16 per chunk.
// smem per stage: A[64pix][32cin] pitch 80B (5120B)
//               + B[256co][32cin] pitch 80B (20480B) = 25600B; 4 stages.

#define PITCH  80
#define A_SZ   5120
#define STAGE  25600
#define NCHUNK 64
#define SMEM_BYTES (4 * STAGE)

__global__ __launch_bounds__(256, 2) void hconv_mma4_kernel(float* __restrict__ out)
{
    extern __shared__ __align__(16) char smem[];
    const uint32_t sb = (uint32_t)__cvta_generic_to_shared(smem);
    float* ep = (float*)smem;     // epilogue reuse: [64 co][68 p]

    const int tid  = threadIdx.x;
    const int lane = tid & 31;
    const int wid  = tid >> 5;
    const int wm = wid & 1;        // warp M index (x32 pixels)
    const int wn = wid >> 1;       // warp N index (x64 couts)

    const int y  = blockIdx.x;            // output row (per parity) 0..63
    const int z  = blockIdx.y;            // b*4 + parity
    const int b  = z >> 2;
    const int py = (z >> 1) & 1;
    const int px = z & 1;

    // ---- A loader: thread -> (pixel, 16B quarter) ----
    const int apix = tid >> 2;            // 0..63
    const int aq   = tid & 3;
    // ---- B loader: thread -> cout row, 4 quarters ----

    // taps for this row/parity
    int kyA[2], iyA[2], kxA[2], dxA[2];
    if (py == 0) { kyA[0] = 1; iyA[0] = y;     kyA[1] = 3; iyA[1] = y - 1; }
    else         { kyA[0] = 0; iyA[0] = y + 1; kyA[1] = 2; iyA[1] = y;     }
    if (px == 0) { kxA[0] = 1; dxA[0] = 0;      kxA[1] = 3; dxA[1] = -1;   }
    else         { kxA[0] = 0; dxA[0] = 1;      kxA[1] = 2; dxA[1] = 0;    }

    const char* asrc[4]; uint32_t asz[4]; int wtap[4];
    #pragma unroll
    for (int tt = 0; tt < 4; ++tt) {
        const int tyi = tt >> 1, txi = tt & 1;
        const int iy = iyA[tyi];
        const int ix = apix + dxA[txi];
        const bool ok = (unsigned)iy < (unsigned)HIN && (unsigned)ix < (unsigned)HIN;
        asz[tt]  = ok ? 16u : 0u;
        asrc[tt] = (const char*)XTH
                 + ((long long)(b * 64 + (ok ? iy : 0)) * 64 + (ok ? ix : 0)) * 1024
                 + aq * 16;
        wtap[tt] = kyA[tyi] * 4 + kxA[txi];
    }
    const char* wbase = (const char*)WHI + (long long)tid * 1024;  // cout=tid

    const uint32_t dA0 = sb + apix * PITCH + aq * 16;
    const uint32_t dB0 = sb + A_SZ + tid * PITCH;

    // ldmatrix row offsets (invariant)
    const int mrow  = (lane & 7) + 8 * ((lane >> 3) & 1);
    const int khalf = lane >> 4;
    uint32_t a_off[2], b_off[4];
    #pragma unroll
    for (int mt = 0; mt < 2; ++mt)
        a_off[mt] = (wm * 32 + mt * 16 + mrow) * PITCH + khalf * 16;
    #pragma unroll
    for (int pr = 0; pr < 4; ++pr)
        b_off[pr] = (wn * 64 + pr * 16 + mrow) * PITCH + khalf * 16;

    float acc[2][8][4];
    #pragma unroll
    for (int mt = 0; mt < 2; ++mt)
        #pragma unroll
        for (int nt = 0; nt < 8; ++nt)
            #pragma unroll
            for (int r = 0; r < 4; ++r) acc[mt][nt][r] = 0.0f;

    #define ISSUE(chunk, stage) do {                                          \
        const int _tap = (chunk) >> 4;                                        \
        const int _c0b = ((chunk) & 15) * 64;        /* 32 cin * 2B */        \
        const char* _xs = ((_tap == 0) ? asrc[0] : (_tap == 1) ? asrc[1]      \
                         : (_tap == 2) ? asrc[2] : asrc[3]) + _c0b;           \
        const uint32_t _sz = (_tap == 0) ? asz[0] : (_tap == 1) ? asz[1]      \
                           : (_tap == 2) ? asz[2] : asz[3];                   \
        const int _wt = (_tap == 0) ? wtap[0] : (_tap == 1) ? wtap[1]         \
                      : (_tap == 2) ? wtap[2] : wtap[3];                      \
        cp16(dA0 + (stage) * STAGE, _xs, _sz);                                \
        const char* _ws = wbase + (long long)_wt * (256 * 1024) + _c0b;       \
        const uint32_t _dB = dB0 + (stage) * STAGE;                           \
        cp16(_dB,      _ws,      16u);                                        \
        cp16(_dB + 16, _ws + 16, 16u);                                        \
        cp16(_dB + 32, _ws + 32, 16u);                                        \
        cp16(_dB + 48, _ws + 48, 16u);                                        \
        CP_COMMIT();                                                          \
    } while (0)

    ISSUE(0, 0);
    ISSUE(1, 1);
    ISSUE(2, 2);

    for (int i = 0; i < NCHUNK; ++i) {
        const int st = i & 3;
        CP_WAIT(2);
        __syncthreads();
        if (i + 3 < NCHUNK) ISSUE(i + 3, (i + 3) & 3);

        const uint32_t Ab = sb + st * STAGE;
        const uint32_t Bb = Ab + A_SZ;
        #pragma unroll
        for (int ks = 0; ks < 2; ++ks) {
            uint32_t af[2][4], bf[8][2];
            #pragma unroll
            for (int pr = 0; pr < 4; ++pr) {
                uint32_t r0, r1, r2, r3;
                ldsm4(r0, r1, r2, r3, Bb + b_off[pr] + ks * 32);
                bf[pr * 2][0] = r0;     bf[pr * 2][1] = r2;
                bf[pr * 2 + 1][0] = r1; bf[pr * 2 + 1][1] = r3;
            }
            #pragma unroll
            for (int mt = 0; mt < 2; ++mt)
                ldsm4(af[mt][0], af[mt][1], af[mt][2], af[mt][3],
                      Ab + a_off[mt] + ks * 32);
            #pragma unroll
            for (int mt = 0; mt < 2; ++mt)
                #pragma unroll
                for (int nt = 0; nt < 8; ++nt)
                    mma16816(acc[mt][nt], af[mt], bf[nt][0], bf[nt][1]);
        }
    }
    CP_WAIT(0);

    // ---- epilogue: stage [64 co][64 p] chunks through smem ----
    const long long outb = (long long)b * COUT * (HOUT * HOUT);
    const int oy = 2 * y + py;
    for (int cb = 0; cb < 4; ++cb) {
        __syncthreads();
        if (wn == cb) {
            #pragma unroll
            for (int mt = 0; mt < 2; ++mt) {
                const int row0 = wm * 32 + mt * 16 + (lane >> 2);
                #pragma unroll
                for (int nt = 0; nt < 8; ++nt) {
                    const int col0 = nt * 8 + (lane & 3) * 2;
                    ep[col0 * 68 + row0]           = acc[mt][nt][0];
                    ep[(col0 + 1) * 68 + row0]     = acc[mt][nt][1];
                    ep[col0 * 68 + row0 + 8]       = acc[mt][nt][2];
                    ep[(col0 + 1) * 68 + row0 + 8] = acc[mt][nt][3];
                }
            }
        }
        __syncthreads();
        // 16 contiguous pixels per thread, stride-2 ox stores
        const int co_l = tid >> 2;
        const int p0   = (tid & 3) * 16;
        const int co   = cb * 64 + co_l;
        const float bias = BBIG[co];
        float* op = out + outb + ((long long)co * HOUT + oy) * HOUT + px;
        #pragma unroll
        for (int j = 0; j < 16; ++j)
            op[2 * (p0 + j)] = ep[co_l * 68 + p0 + j] + bias;
    }
}

// ---------------- host launcher ----------------

extern "C" void kernel_launch(void* const* d_in, const int* in_sizes, int n_in,
                              void* d_out, int out_size)
{
    const float* x  = (const float*)d_in[0];
    const float* W  = (const float*)d_in[1];
    const float* bb = (const float*)d_in[2];
    float* out = (float*)d_out;

    // Cayley-Dickson component table (host-side, passed by value: no memcpy)
    CompT comp;
    comp.v[0][0] = 0;
    for (int m = 1; m < 8; m <<= 1)
        for (int i = 0; i < m; ++i)
            for (int j = 0; j < m; ++j) {
                const int a = comp.v[i][j];
                comp.v[i][j + m] = -(a + m);
                comp.v[i + m][j] = a + m;
                comp.v[i + m][j + m] = a;
            }

    cudaFuncSetAttribute(hconv_mma4_kernel,
                         cudaFuncAttributeMaxDynamicSharedMemorySize, SMEM_BYTES);

    prep_x_kernel<<<2048, 256>>>(x);
    prep_w_kernel<<<(WELEMS + 255) / 256, 256>>>(W, comp);
    prep_b_kernel<<<1, 256>>>(bb, comp);

    dim3 grid(64, 32);   // (output rows, batch*parity)
    hconv_mma4_kernel<<<grid, 256, SMEM_BYTES>>>(out);
}